// round 3
// baseline (speedup 1.0000x reference)
#include <cuda_runtime.h>
#include <cuda_fp16.h>
#include <cstdint>
#include <cstddef>

#define TLEN 4096
#define NB   32
#define HD   256

// Scratch (device globals: allocation-free rule)
static __device__ __align__(256) float g_Xp [TLEN * NB * HD];  // 134 MB, reused per layer
static __device__ __align__(256) float g_H0f[TLEN * NB * HD];  // 134 MB, layer-0 outputs

// ---------------------------------------------------------------------------
// Fast, accurate tanh: (e^(2x)-1)/(e^(2x)+1) with MUFU EX2 (+clamp). ~1e-6 err.
__device__ __forceinline__ float tanh_fast(float x) {
    float cx = fminf(fmaxf(x, -9.0f), 9.0f);
    float e  = exp2f(cx * 2.8853900817779268f);   // 2*log2(e)
    return __fdividef(e - 1.0f, e + 1.0f);
}

__device__ __forceinline__ uint32_t pack_h2(float lo, float hi) {
    __half2 h = __floats2half2_rn(lo, hi);
    return *reinterpret_cast<uint32_t*>(&h);
}

// ---------------------------------------------------------------------------
// Scan kernel: h[t] = tanh(Xp[t] + W_hh * h[t-1]) for one group of 8 batch rows.
// D[M=256 hidden, N=8 batch] via mma.sync.m16n8k16 (fp16 in, fp32 acc).
// W_hh is fully register-resident as A fragments (128 regs/thread).
// h state: SMEM fp16, n-major, stride 264 halves (conflict-free), double-buffered.

#define HS_STRIDE 264   // halves per n-row (256 + 8 pad)

__global__ void __launch_bounds__(256, 1) rnn_scan_kernel(
    const float* __restrict__ Xp,   // [T*NB, HD] pre-activations (input path + biases)
    const float* __restrict__ Whh,  // [HD, HD] fp32, this layer
    const float* __restrict__ h0,   // [NB, HD] fp32, this layer
    float* __restrict__ Out)        // [T*NB, HD] fp32
{
    __shared__ __align__(16) __half hs[2][8][HS_STRIDE];

    const int tid  = threadIdx.x;
    const int w    = tid >> 5;        // warp 0..7 -> hidden rows [32w, 32w+32)
    const int lane = tid & 31;
    const int grp  = lane >> 2;       // 0..7
    const int tid4 = lane & 3;        // 0..3
    const int b0   = blockIdx.x * 8;  // batch base

    // ---- Build A fragments (W_hh fp32 -> fp16), register-resident -----------
    // mma.m16n8k16 A frag (row-major 16x16):
    //   a0: (grp,        tid4*2+{0,1})      a1: (grp+8, same)
    //   a2: (grp,        tid4*2+8+{0,1})    a3: (grp+8, same)
    uint32_t afr[2][16][4];
    #pragma unroll
    for (int mt = 0; mt < 2; ++mt) {
        const int r0 = w * 32 + mt * 16 + grp;
        #pragma unroll
        for (int kt = 0; kt < 16; ++kt) {
            const int k0 = kt * 16 + tid4 * 2;
            const float* p0 = Whh + (size_t)r0 * HD + k0;
            const float* p1 = Whh + (size_t)(r0 + 8) * HD + k0;
            afr[mt][kt][0] = pack_h2(p0[0], p0[1]);
            afr[mt][kt][1] = pack_h2(p1[0], p1[1]);
            afr[mt][kt][2] = pack_h2(p0[8], p0[9]);
            afr[mt][kt][3] = pack_h2(p1[8], p1[9]);
        }
    }

    // ---- Stage h0 into buffer 0 ---------------------------------------------
    for (int idx = tid; idx < 8 * HD; idx += 256) {
        const int n = idx >> 8, k = idx & 255;
        hs[0][n][k] = __float2half_rn(h0[(size_t)(b0 + n) * HD + k]);
    }
    __syncthreads();

    // Epilogue / Xp indexing for this thread:
    //   D row m = w*32 + mt*16 + grp (+8), col n = tid4*2 (+1)
    const int m0 = w * 32 + grp;        // mt=0 row base (mt=1 adds 16)
    const int n0 = tid4 * 2;

    for (int t = 0; t < TLEN; ++t) {
        const int rd = t & 1;
        const int wr = rd ^ 1;

        // ---- prefetch Xp[t] (8 scalars) before the MMAs ----
        const float* xrow = Xp + ((size_t)t * NB + b0) * HD;
        float xp[2][4];
        #pragma unroll
        for (int mt = 0; mt < 2; ++mt) {
            const int m = m0 + mt * 16;
            xp[mt][0] = __ldcs(xrow + (size_t)(n0    ) * HD + m);
            xp[mt][1] = __ldcs(xrow + (size_t)(n0 + 1) * HD + m);
            xp[mt][2] = __ldcs(xrow + (size_t)(n0    ) * HD + m + 8);
            xp[mt][3] = __ldcs(xrow + (size_t)(n0 + 1) * HD + m + 8);
        }

        // ---- MMAs: D[2 mtiles] = sum_k A[mt][kt] * B[kt] ----
        float c[2][4] = {};
        #pragma unroll
        for (int kt = 0; kt < 16; ++kt) {
            // B frag: b0 = h[k = kt*16 + tid4*2 + {0,1}][n = grp], b1 = +8 in k
            const __half* bp = &hs[rd][grp][kt * 16 + tid4 * 2];
            const uint32_t bf0 = *reinterpret_cast<const uint32_t*>(bp);
            const uint32_t bf1 = *reinterpret_cast<const uint32_t*>(bp + 8);
            #pragma unroll
            for (int mt = 0; mt < 2; ++mt) {
                asm volatile(
                    "mma.sync.aligned.m16n8k16.row.col.f32.f16.f16.f32 "
                    "{%0,%1,%2,%3}, {%4,%5,%6,%7}, {%8,%9}, {%0,%1,%2,%3};"
                    : "+f"(c[mt][0]), "+f"(c[mt][1]), "+f"(c[mt][2]), "+f"(c[mt][3])
                    : "r"(afr[mt][kt][0]), "r"(afr[mt][kt][1]),
                      "r"(afr[mt][kt][2]), "r"(afr[mt][kt][3]),
                      "r"(bf0), "r"(bf1));
            }
        }

        // ---- epilogue: tanh(D + Xp) -> h (fp16 smem) + Out (fp32 gmem) ----
        float* orow = Out + ((size_t)t * NB + b0) * HD;
        #pragma unroll
        for (int mt = 0; mt < 2; ++mt) {
            const int m = m0 + mt * 16;
            const float v0 = tanh_fast(c[mt][0] + xp[mt][0]);  // (m,   n0)
            const float v1 = tanh_fast(c[mt][1] + xp[mt][1]);  // (m,   n0+1)
            const float v2 = tanh_fast(c[mt][2] + xp[mt][2]);  // (m+8, n0)
            const float v3 = tanh_fast(c[mt][3] + xp[mt][3]);  // (m+8, n0+1)
            hs[wr][n0    ][m]     = __float2half_rn(v0);
            hs[wr][n0 + 1][m]     = __float2half_rn(v1);
            hs[wr][n0    ][m + 8] = __float2half_rn(v2);
            hs[wr][n0 + 1][m + 8] = __float2half_rn(v3);
            __stcs(orow + (size_t)(n0    ) * HD + m,     v0);
            __stcs(orow + (size_t)(n0 + 1) * HD + m,     v1);
            __stcs(orow + (size_t)(n0    ) * HD + m + 8, v2);
            __stcs(orow + (size_t)(n0 + 1) * HD + m + 8, v3);
        }
        __syncthreads();
    }
}

// --------------------------- input-path GEMM --------------------------------
// Out[r, h] = sum_d In[r, d] * W[h, d] + bi[h] + bh[h]
// M = T*NB rows, N = K = 256.  BM=64, BN=64, BK=16, 256 threads, 4x4 microtile.
#define BM 64
#define BN 64
#define BK 16

__global__ void __launch_bounds__(256) gemm_xw_kernel(
    const float* __restrict__ In, const float* __restrict__ W,
    const float* __restrict__ bi, const float* __restrict__ bh,
    float* __restrict__ Out)
{
    __shared__ float As[BM][BK + 1];
    __shared__ float Bs[BN][BK + 1];

    const int row0 = blockIdx.y * BM;
    const int col0 = blockIdx.x * BN;
    const int tid  = threadIdx.x;
    const int tx   = tid & 15;       // 0..15 -> 4 output cols
    const int ty   = tid >> 4;       // 0..15 -> 4 output rows

    float acc[4][4] = {};

    const int lr = tid >> 2;         // 0..63 tile row to load
    const int lc = (tid & 3) << 2;   // 0,4,8,12

    for (int k0 = 0; k0 < HD; k0 += BK) {
        float4 a = *(const float4*)&In[(size_t)(row0 + lr) * HD + k0 + lc];
        float4 b = *(const float4*)&W [(size_t)(col0 + lr) * HD + k0 + lc];
        As[lr][lc] = a.x; As[lr][lc + 1] = a.y; As[lr][lc + 2] = a.z; As[lr][lc + 3] = a.w;
        Bs[lr][lc] = b.x; Bs[lr][lc + 1] = b.y; Bs[lr][lc + 2] = b.z; Bs[lr][lc + 3] = b.w;
        __syncthreads();
        #pragma unroll
        for (int kk = 0; kk < BK; ++kk) {
            float av[4], bv[4];
            #pragma unroll
            for (int i = 0; i < 4; ++i) av[i] = As[ty * 4 + i][kk];
            #pragma unroll
            for (int j = 0; j < 4; ++j) bv[j] = Bs[tx * 4 + j][kk];
            #pragma unroll
            for (int i = 0; i < 4; ++i)
                #pragma unroll
                for (int j = 0; j < 4; ++j) acc[i][j] += av[i] * bv[j];
        }
        __syncthreads();
    }

    #pragma unroll
    for (int j = 0; j < 4; ++j) {
        const int c = col0 + tx * 4 + j;
        const float bias = bi[c] + bh[c];
        #pragma unroll
        for (int i = 0; i < 4; ++i)
            Out[(size_t)(row0 + ty * 4 + i) * HD + c] = acc[i][j] + bias;
    }
}

// -------------------------------- launcher ----------------------------------
extern "C" void kernel_launch(void* const* d_in, const int* in_sizes, int n_in,
                              void* d_out, int out_size) {
    const float* x    = (const float*)d_in[0];  // [T,B,D]
    const float* W_ih = (const float*)d_in[1];  // [L,H,D]
    const float* W_hh = (const float*)d_in[2];  // [L,H,H]
    const float* b_ih = (const float*)d_in[3];  // [L,H]
    const float* b_hh = (const float*)d_in[4];  // [L,H]
    const float* h0   = (const float*)d_in[5];  // [L,B,H]
    float* out = (float*)d_out;                 // [T,B,H]

    float* Xp  = nullptr;
    float* H0f = nullptr;
    cudaGetSymbolAddress((void**)&Xp,  g_Xp);
    cudaGetSymbolAddress((void**)&H0f, g_H0f);

    const dim3 gemm_grid(HD / BN, (TLEN * NB) / BM);

    // Layer 0
    gemm_xw_kernel<<<gemm_grid, 256>>>(x, W_ih, b_ih, b_hh, Xp);
    rnn_scan_kernel<<<4, 256>>>(Xp, W_hh, h0, H0f);
    // Layer 1
    gemm_xw_kernel<<<gemm_grid, 256>>>(H0f, W_ih + HD * HD, b_ih + HD, b_hh + HD, Xp);
    rnn_scan_kernel<<<4, 256>>>(Xp, W_hh + HD * HD, h0 + NB * HD, out);
}

// round 4
// speedup vs baseline: 1.3440x; 1.3440x over previous
#include <cuda_runtime.h>
#include <cuda_fp16.h>
#include <cstdint>
#include <cstddef>

#define TLEN 4096
#define NB   32
#define HD   256
#define HS   264   // smem halves per n-row (256 + 8 pad, conflict-free b-frags)

// Scratch (device globals: allocation-free rule)
static __device__ __align__(256) float  g_Xp0[(size_t)TLEN * NB * HD]; // frag-layout preacts L0
static __device__ __align__(256) float  g_Xp1[(size_t)TLEN * NB * HD]; // frag-layout preacts L1
static __device__ __align__(256) __half g_H0h[(size_t)TLEN * NB * HD]; // L0 hidden, [t][cid][n][256] fp16
static __device__ int g_progA[4];
static __device__ int g_progB[4];

// ---------------------------------------------------------------------------
__device__ __forceinline__ float tanh_fast(float x) {
    float cx = fminf(fmaxf(x, -9.0f), 9.0f);
    float e  = exp2f(cx * 2.8853900817779268f);   // 2*log2(e)
    return __fdividef(e - 1.0f, e + 1.0f);
}
__device__ __forceinline__ uint32_t pack_h2(float lo, float hi) {
    __half2 h = __floats2half2_rn(lo, hi);
    return *reinterpret_cast<uint32_t*>(&h);
}
__device__ __forceinline__ int ld_vol(const int* p) {
    int v;
    asm volatile("ld.volatile.global.s32 %0, [%1];" : "=r"(v) : "l"(p));
    return v;
}
__device__ __forceinline__ void st_vol(int* p, int v) {
    asm volatile("st.volatile.global.s32 [%0], %1;" :: "l"(p), "r"(v));
}
#define HMMA(acc, af, bf0, bf1)                                               \
    asm volatile(                                                             \
        "mma.sync.aligned.m16n8k16.row.col.f32.f16.f16.f32 "                  \
        "{%0,%1,%2,%3}, {%4,%5,%6,%7}, {%8,%9}, {%0,%1,%2,%3};"               \
        : "+f"((acc)[0]), "+f"((acc)[1]), "+f"((acc)[2]), "+f"((acc)[3])      \
        : "r"((af)[0]), "r"((af)[1]), "r"((af)[2]), "r"((af)[3]),             \
          "r"(bf0), "r"(bf1))

// Load register-resident A fragments for a 32-row slice of a 256x256 fp32 weight.
__device__ __forceinline__ void load_frags(uint32_t afr[2][16][4],
                                           const float* __restrict__ W,
                                           int w, int grp, int tid4) {
    #pragma unroll
    for (int mt = 0; mt < 2; ++mt) {
        const int r0 = w * 32 + mt * 16 + grp;
        #pragma unroll
        for (int kt = 0; kt < 16; ++kt) {
            const int k0 = kt * 16 + tid4 * 2;
            const float* p0 = W + (size_t)r0 * HD + k0;
            const float* p1 = W + (size_t)(r0 + 8) * HD + k0;
            afr[mt][kt][0] = pack_h2(p0[0], p0[1]);
            afr[mt][kt][1] = pack_h2(p1[0], p1[1]);
            afr[mt][kt][2] = pack_h2(p0[8], p0[9]);
            afr[mt][kt][3] = pack_h2(p1[8], p1[9]);
        }
    }
}

// ---------------------------------------------------------------------------
// Fused 3-stage pipelined kernel.  grid = 12 CTAs x 256 threads:
//   CTA 0-3  (A): layer-0 recurrence, publishes h0(t) fp16 tiles
//   CTA 4-7  (B): projection xp1(t) = W_ih1 * h0(t) + bias (double-stepped)
//   CTA 8-11 (C): layer-1 recurrence, writes final Out
__global__ void __launch_bounds__(256, 1) rnn_fused_kernel(
    const float* __restrict__ Whh0, const float* __restrict__ Whh1,
    const float* __restrict__ Wih1,
    const float* __restrict__ b_ih, const float* __restrict__ b_hh,
    const float* __restrict__ h0all, float* __restrict__ Out)
{
    __shared__ __align__(16) __half hsA[2][8][HS];   // A/C: h state (dbl-buf); B: staged tiles
    __shared__ __align__(16) float  obuf[2][8][HS];  // C only: output staging

    const int tid  = threadIdx.x;
    const int w    = tid >> 5;
    const int lane = tid & 31;
    const int grp  = lane >> 2;
    const int tid4 = lane & 3;
    const int role = blockIdx.x >> 2;   // 0=A, 1=B, 2=C
    const int cid  = blockIdx.x & 3;
    const int b0   = cid * 8;
    const int m0   = w * 32 + grp;
    const int n0   = tid4 * 2;

    // ======================= Stage A: layer-0 recurrence ====================
    if (role == 0) {
        uint32_t afr[2][16][4];
        load_frags(afr, Whh0, w, grp, tid4);

        for (int idx = tid; idx < 8 * HD; idx += 256) {
            const int n = idx >> 8, k = idx & 255;
            hsA[0][n][k] = __float2half_rn(h0all[(size_t)(b0 + n) * HD + k]);
        }
        __syncthreads();

        const size_t fb = ((size_t)cid * 8 + w) * 256 + lane * 8;
        float4 xc0 = *(const float4*)(g_Xp0 + fb);
        float4 xc1 = *(const float4*)(g_Xp0 + fb + 4);

        for (int u = 0; u <= TLEN; ++u) {
            const int rd = u & 1, wr = rd ^ 1;

            // publish h0(u-1): coalesced fp16 tile copy smem -> gmem
            if (u > 0) {
                const int n = tid >> 5, kb = (tid & 31) * 8;
                uint4 v = *(const uint4*)&hsA[rd][n][kb];
                *(uint4*)((char*)g_H0h +
                          ((((size_t)(u - 1) * 4 + cid) * 8 + n) * 512) + kb * 2) = v;
            }

            if (u < TLEN) {
                float c[2][4] = {}, c2[2][4] = {};
                #pragma unroll
                for (int kt = 0; kt < 16; ++kt) {
                    const __half* bp = &hsA[rd][grp][kt * 16 + tid4 * 2];
                    const uint32_t bf0 = *(const uint32_t*)bp;
                    const uint32_t bf1 = *(const uint32_t*)(bp + 8);
                    if (kt & 1) { HMMA(c2[0], afr[0][kt], bf0, bf1); HMMA(c2[1], afr[1][kt], bf0, bf1); }
                    else        { HMMA(c [0], afr[0][kt], bf0, bf1); HMMA(c [1], afr[1][kt], bf0, bf1); }
                }
                // prefetch next-step Xp0 behind the MMAs
                const int tn = (u + 1 < TLEN) ? u + 1 : TLEN - 1;
                const float* pn = g_Xp0 + ((size_t)tn * 4 * 8 * 32 * 8) + fb;
                float4 xn0 = *(const float4*)pn;
                float4 xn1 = *(const float4*)(pn + 4);

                const float* xc = (const float*)&xc0;  // [mt=0][i]
                const float* xd = (const float*)&xc1;  // [mt=1][i]
                #pragma unroll
                for (int i = 0; i < 4; ++i) {
                    const int n = n0 + (i & 1);
                    const int mo = (i >> 1) * 8;
                    float v0 = tanh_fast(c[0][i] + c2[0][i] + xc[i]);
                    float v1 = tanh_fast(c[1][i] + c2[1][i] + xd[i]);
                    hsA[wr][n][m0 + mo]      = __float2half_rn(v0);
                    hsA[wr][n][m0 + 16 + mo] = __float2half_rn(v1);
                }
                xc0 = xn0; xc1 = xn1;
            }
            __threadfence();
            __syncthreads();
            if (tid == 0) st_vol(&g_progA[cid], u);
        }
    }
    // ======================= Stage B: xp1 projection ========================
    else if (role == 1) {
        uint32_t afr[2][16][4];
        load_frags(afr, Wih1, w, grp, tid4);
        float bias[2][2];
        #pragma unroll
        for (int mt = 0; mt < 2; ++mt)
            #pragma unroll
            for (int ih = 0; ih < 2; ++ih) {
                const int m = m0 + mt * 16 + ih * 8;
                bias[mt][ih] = b_ih[HD + m] + b_hh[HD + m];
            }

        const int ln = tid >> 5, kb = (tid & 31) * 8;

        for (int tp = 0; tp < TLEN; tp += 2) {
            if (tid == 0) { while (ld_vol(&g_progA[cid]) < tp + 2) {} }
            __syncthreads();
            __threadfence();

            // stage two h0 tiles into smem (coalesced)
            uint4 v0 = *(const uint4*)((const char*)g_H0h +
                        ((((size_t)tp * 4 + cid) * 8 + ln) * 512) + kb * 2);
            uint4 v1 = *(const uint4*)((const char*)g_H0h +
                        ((((size_t)(tp + 1) * 4 + cid) * 8 + ln) * 512) + kb * 2);
            *(uint4*)&hsA[0][ln][kb] = v0;
            *(uint4*)&hsA[1][ln][kb] = v1;
            __syncthreads();

            #pragma unroll
            for (int s = 0; s < 2; ++s) {
                float c[2][4] = {}, c2[2][4] = {};
                #pragma unroll
                for (int kt = 0; kt < 16; ++kt) {
                    const __half* bp = &hsA[s][grp][kt * 16 + tid4 * 2];
                    const uint32_t bf0 = *(const uint32_t*)bp;
                    const uint32_t bf1 = *(const uint32_t*)(bp + 8);
                    if (kt & 1) { HMMA(c2[0], afr[0][kt], bf0, bf1); HMMA(c2[1], afr[1][kt], bf0, bf1); }
                    else        { HMMA(c [0], afr[0][kt], bf0, bf1); HMMA(c [1], afr[1][kt], bf0, bf1); }
                }
                float* ob = g_Xp1 + (((size_t)(tp + s) * 4 + cid) * 8 + w) * 256 + lane * 8;
                float4 o0, o1;
                ((float*)&o0)[0] = c[0][0] + c2[0][0] + bias[0][0];
                ((float*)&o0)[1] = c[0][1] + c2[0][1] + bias[0][0];
                ((float*)&o0)[2] = c[0][2] + c2[0][2] + bias[0][1];
                ((float*)&o0)[3] = c[0][3] + c2[0][3] + bias[0][1];
                ((float*)&o1)[0] = c[1][0] + c2[1][0] + bias[1][0];
                ((float*)&o1)[1] = c[1][1] + c2[1][1] + bias[1][0];
                ((float*)&o1)[2] = c[1][2] + c2[1][2] + bias[1][1];
                ((float*)&o1)[3] = c[1][3] + c2[1][3] + bias[1][1];
                *(float4*)ob = o0;
                *(float4*)(ob + 4) = o1;
            }
            __threadfence();
            __syncthreads();
            if (tid == 0) st_vol(&g_progB[cid], tp + 2);
        }
    }
    // ======================= Stage C: layer-1 recurrence ====================
    else {
        uint32_t afr[2][16][4];
        load_frags(afr, Whh1, w, grp, tid4);

        const float* h0l1 = h0all + (size_t)NB * HD;
        for (int idx = tid; idx < 8 * HD; idx += 256) {
            const int n = idx >> 8, k = idx & 255;
            hsA[0][n][k] = __float2half_rn(h0l1[(size_t)(b0 + n) * HD + k]);
        }
        __syncthreads();

        while (ld_vol(&g_progB[cid]) < 1) {}
        __threadfence();
        const size_t fb = ((size_t)cid * 8 + w) * 256 + lane * 8;
        float4 xc0 = *(const float4*)(g_Xp1 + fb);
        float4 xc1 = *(const float4*)(g_Xp1 + fb + 4);

        for (int u = 0; u <= TLEN; ++u) {
            const int rd = u & 1, wr = rd ^ 1;

            // flush Out(u-1): coalesced fp32 copy from staging buffer
            if (u > 0) {
                const int n = tid >> 5, kb = (tid & 31) * 8;
                float4 a = *(const float4*)&obuf[rd][n][kb];
                float4 b = *(const float4*)&obuf[rd][n][kb + 4];
                float* dst = Out + ((size_t)(u - 1) * NB + b0 + n) * HD + kb;
                *(float4*)dst = a;
                *(float4*)(dst + 4) = b;
            }

            if (u < TLEN) {
                float c[2][4] = {}, c2[2][4] = {};
                #pragma unroll
                for (int kt = 0; kt < 16; ++kt) {
                    const __half* bp = &hsA[rd][grp][kt * 16 + tid4 * 2];
                    const uint32_t bf0 = *(const uint32_t*)bp;
                    const uint32_t bf1 = *(const uint32_t*)(bp + 8);
                    if (kt & 1) { HMMA(c2[0], afr[0][kt], bf0, bf1); HMMA(c2[1], afr[1][kt], bf0, bf1); }
                    else        { HMMA(c [0], afr[0][kt], bf0, bf1); HMMA(c [1], afr[1][kt], bf0, bf1); }
                }
                // prefetch xp1(u+1) behind the MMAs (flag check then load)
                const int tn = (u + 1 < TLEN) ? u + 1 : TLEN - 1;
                while (ld_vol(&g_progB[cid]) < tn + 1) {}
                __threadfence();
                const float* pn = g_Xp1 + ((size_t)tn * 4 * 8 * 32 * 8) + fb;
                float4 xn0 = *(const float4*)pn;
                float4 xn1 = *(const float4*)(pn + 4);

                const float* xc = (const float*)&xc0;
                const float* xd = (const float*)&xc1;
                #pragma unroll
                for (int i = 0; i < 4; ++i) {
                    const int n = n0 + (i & 1);
                    const int mo = (i >> 1) * 8;
                    float v0 = tanh_fast(c[0][i] + c2[0][i] + xc[i]);
                    float v1 = tanh_fast(c[1][i] + c2[1][i] + xd[i]);
                    hsA[wr][n][m0 + mo]       = __float2half_rn(v0);
                    hsA[wr][n][m0 + 16 + mo]  = __float2half_rn(v1);
                    obuf[wr][n][m0 + mo]      = v0;
                    obuf[wr][n][m0 + 16 + mo] = v1;
                }
                xc0 = xn0; xc1 = xn1;
            }
            __syncthreads();
        }
    }
}

// --------------------------- input-path GEMM (layer 0) ----------------------
// Xp0[t,b,h] = sum_d x[t,b,d] * W_ih0[h,d] + bi[h] + bh[h], stored FRAG-LAYOUT.
#define BM 64
#define BN 64
#define BK 16

__global__ void __launch_bounds__(256) gemm_xw_kernel(
    const float* __restrict__ In, const float* __restrict__ W,
    const float* __restrict__ bi, const float* __restrict__ bh,
    float* __restrict__ OutF)
{
    __shared__ float As[BM][BK + 1];
    __shared__ float Bs[BN][BK + 1];

    const int row0 = blockIdx.y * BM;
    const int col0 = blockIdx.x * BN;
    const int tid  = threadIdx.x;

    if (blockIdx.x == 0 && blockIdx.y == 0 && tid == 0) {
        #pragma unroll
        for (int i = 0; i < 4; ++i) { g_progA[i] = 0; g_progB[i] = 0; }
    }

    const int tx = tid & 15;
    const int ty = tid >> 4;

    float acc[4][4] = {};

    const int lr = tid >> 2;
    const int lc = (tid & 3) << 2;

    for (int k0 = 0; k0 < HD; k0 += BK) {
        float4 a = *(const float4*)&In[(size_t)(row0 + lr) * HD + k0 + lc];
        float4 b = *(const float4*)&W [(size_t)(col0 + lr) * HD + k0 + lc];
        As[lr][lc] = a.x; As[lr][lc + 1] = a.y; As[lr][lc + 2] = a.z; As[lr][lc + 3] = a.w;
        Bs[lr][lc] = b.x; Bs[lr][lc + 1] = b.y; Bs[lr][lc + 2] = b.z; Bs[lr][lc + 3] = b.w;
        __syncthreads();
        #pragma unroll
        for (int kk = 0; kk < BK; ++kk) {
            float av[4], bv[4];
            #pragma unroll
            for (int i = 0; i < 4; ++i) av[i] = As[ty * 4 + i][kk];
            #pragma unroll
            for (int j = 0; j < 4; ++j) bv[j] = Bs[tx * 4 + j][kk];
            #pragma unroll
            for (int i = 0; i < 4; ++i)
                #pragma unroll
                for (int j = 0; j < 4; ++j) acc[i][j] += av[i] * bv[j];
        }
        __syncthreads();
    }

    #pragma unroll
    for (int j = 0; j < 4; ++j) {
        const int h = col0 + tx * 4 + j;
        const float bias = bi[h] + bh[h];
        const int wA  = h >> 5, mt = (h >> 4) & 1, ihi = (h >> 3) & 1, grpA = h & 7;
        #pragma unroll
        for (int i = 0; i < 4; ++i) {
            const int r = row0 + ty * 4 + i;
            const int t = r >> 5, b = r & 31;
            const int cta = b >> 3, n = b & 7;
            const int laneA = grpA * 4 + (n >> 1);
            const int jA = mt * 4 + ihi * 2 + (n & 1);
            OutF[((((size_t)t * 4 + cta) * 8 + wA) * 32 + laneA) * 8 + jA] = acc[i][j] + bias;
        }
    }
}

// -------------------------------- launcher ----------------------------------
extern "C" void kernel_launch(void* const* d_in, const int* in_sizes, int n_in,
                              void* d_out, int out_size) {
    const float* x    = (const float*)d_in[0];  // [T,B,D]
    const float* W_ih = (const float*)d_in[1];  // [L,H,D]
    const float* W_hh = (const float*)d_in[2];  // [L,H,H]
    const float* b_ih = (const float*)d_in[3];  // [L,H]
    const float* b_hh = (const float*)d_in[4];  // [L,H]
    const float* h0   = (const float*)d_in[5];  // [L,B,H]
    float* out = (float*)d_out;                 // [T,B,H]

    float* Xp0 = nullptr;
    cudaGetSymbolAddress((void**)&Xp0, g_Xp0);

    const dim3 gemm_grid(HD / BN, (TLEN * NB) / BM);

    gemm_xw_kernel<<<gemm_grid, 256>>>(x, W_ih, b_ih, b_hh, Xp0);
    rnn_fused_kernel<<<12, 256>>>(W_hh, W_hh + HD * HD, W_ih + HD * HD,
                                  b_ih, b_hh, h0, out);
}

// round 5
// speedup vs baseline: 1.7713x; 1.3179x over previous
#include <cuda_runtime.h>
#include <cuda_fp16.h>
#include <cstdint>
#include <cstddef>

#define TLEN 4096
#define NB   32
#define HD   256
#define HS   264   // smem halves per n-row (256 + 8 pad, conflict-free b-frags)

// Scratch (device globals: allocation-free rule)
static __device__ __align__(256) float  g_Xp0[(size_t)TLEN * NB * HD]; // frag-layout preacts L0
static __device__ __align__(256) float  g_Xp1[(size_t)TLEN * NB * HD]; // frag-layout preacts L1
static __device__ __align__(256) __half g_H0h[(size_t)TLEN * NB * HD]; // L0 hidden, [t][cid][n][256] fp16
static __device__ int g_progA[4];
static __device__ int g_progB[4];

// ---------------------------------------------------------------------------
__device__ __forceinline__ float tanh_fast(float x) {
    float cx = fminf(fmaxf(x, -9.0f), 9.0f);
    float e  = exp2f(cx * 2.8853900817779268f);   // 2*log2(e)
    return __fdividef(e - 1.0f, e + 1.0f);
}
__device__ __forceinline__ uint32_t pack_h2(float lo, float hi) {
    __half2 h = __floats2half2_rn(lo, hi);
    return *reinterpret_cast<uint32_t*>(&h);
}
__device__ __forceinline__ int ld_acq(const int* p) {
    int v;
    asm volatile("ld.acquire.gpu.global.s32 %0, [%1];" : "=r"(v) : "l"(p));
    return v;
}
__device__ __forceinline__ void st_rel(int* p, int v) {
    asm volatile("st.release.gpu.global.s32 [%0], %1;" :: "l"(p), "r"(v));
}
__device__ __forceinline__ void prewait(const int* p, int v) {
    while (ld_acq(p) < v) { __nanosleep(200); }
}
#define HMMA(acc, af, bf0, bf1)                                               \
    asm volatile(                                                             \
        "mma.sync.aligned.m16n8k16.row.col.f32.f16.f16.f32 "                  \
        "{%0,%1,%2,%3}, {%4,%5,%6,%7}, {%8,%9}, {%0,%1,%2,%3};"               \
        : "+f"((acc)[0]), "+f"((acc)[1]), "+f"((acc)[2]), "+f"((acc)[3])      \
        : "r"((af)[0]), "r"((af)[1]), "r"((af)[2]), "r"((af)[3]),             \
          "r"(bf0), "r"(bf1))

// Load register-resident A fragments for a 32-row slice of a 256x256 fp32 weight.
__device__ __forceinline__ void load_frags(uint32_t afr[2][16][4],
                                           const float* __restrict__ W,
                                           int w, int grp, int tid4) {
    #pragma unroll
    for (int mt = 0; mt < 2; ++mt) {
        const int r0 = w * 32 + mt * 16 + grp;
        #pragma unroll
        for (int kt = 0; kt < 16; ++kt) {
            const int k0 = kt * 16 + tid4 * 2;
            const float* p0 = W + (size_t)r0 * HD + k0;
            const float* p1 = W + (size_t)(r0 + 8) * HD + k0;
            afr[mt][kt][0] = pack_h2(p0[0], p0[1]);
            afr[mt][kt][1] = pack_h2(p1[0], p1[1]);
            afr[mt][kt][2] = pack_h2(p0[8], p0[9]);
            afr[mt][kt][3] = pack_h2(p1[8], p1[9]);
        }
    }
}

// ---------------------------------------------------------------------------
// Fused 3-stage pipelined kernel.  grid = 12 CTAs x 256 threads:
//   CTA 0-3  (A): layer-0 recurrence, publishes h0(t) fp16 tiles
//   CTA 4-7  (B): projection xp1(t) = W_ih1 * h0(t) + bias (double-stepped)
//   CTA 8-11 (C): layer-1 recurrence, writes final Out
__global__ void __launch_bounds__(256, 1) rnn_fused_kernel(
    const float* __restrict__ Whh0, const float* __restrict__ Whh1,
    const float* __restrict__ Wih1,
    const float* __restrict__ b_ih, const float* __restrict__ b_hh,
    const float* __restrict__ h0all, float* __restrict__ Out)
{
    __shared__ __align__(16) __half hsA[2][8][HS];   // A/C: h state (dbl-buf); B: staged tiles
    __shared__ __align__(16) float  obuf[2][8][HS];  // C only: output staging

    const int tid  = threadIdx.x;
    const int w    = tid >> 5;
    const int lane = tid & 31;
    const int grp  = lane >> 2;
    const int tid4 = lane & 3;
    const int role = blockIdx.x >> 2;   // 0=A, 1=B, 2=C
    const int cid  = blockIdx.x & 3;
    const int b0   = cid * 8;
    const int m0   = w * 32 + grp;
    const int n0   = tid4 * 2;

    // ======================= Stage A: layer-0 recurrence ====================
    if (role == 0) {
        uint32_t afr[2][16][4];
        load_frags(afr, Whh0, w, grp, tid4);

        for (int idx = tid; idx < 8 * HD; idx += 256) {
            const int n = idx >> 8, k = idx & 255;
            hsA[0][n][k] = __float2half_rn(h0all[(size_t)(b0 + n) * HD + k]);
        }
        __syncthreads();

        const size_t fb = ((size_t)cid * 8 + w) * 256 + lane * 8;
        float4 xc0 = *(const float4*)(g_Xp0 + fb);
        float4 xc1 = *(const float4*)(g_Xp0 + fb + 4);

        for (int u = 0; u <= TLEN; ++u) {
            const int rd = u & 1, wr = rd ^ 1;

            // publish h0(u-1): coalesced fp16 tile copy smem -> gmem
            if (u > 0) {
                const int n = tid >> 5, kb = (tid & 31) * 8;
                uint4 v = *(const uint4*)&hsA[rd][n][kb];
                *(uint4*)((char*)g_H0h +
                          ((((size_t)(u - 1) * 4 + cid) * 8 + n) * 512) + kb * 2) = v;
            }

            if (u < TLEN) {
                float c[2][4] = {}, c2[2][4] = {};
                #pragma unroll
                for (int kt = 0; kt < 16; ++kt) {
                    const __half* bp = &hsA[rd][grp][kt * 16 + tid4 * 2];
                    const uint32_t bf0 = *(const uint32_t*)bp;
                    const uint32_t bf1 = *(const uint32_t*)(bp + 8);
                    if (kt & 1) { HMMA(c2[0], afr[0][kt], bf0, bf1); HMMA(c2[1], afr[1][kt], bf0, bf1); }
                    else        { HMMA(c [0], afr[0][kt], bf0, bf1); HMMA(c [1], afr[1][kt], bf0, bf1); }
                }
                // prefetch next-step Xp0 behind the MMAs
                const int tn = (u + 1 < TLEN) ? u + 1 : TLEN - 1;
                const float* pn = g_Xp0 + ((size_t)tn * 4 * 8 * 32 * 8) + fb;
                float4 xn0 = *(const float4*)pn;
                float4 xn1 = *(const float4*)(pn + 4);

                const float* xc = (const float*)&xc0;  // [mt=0][i]
                const float* xd = (const float*)&xc1;  // [mt=1][i]
                #pragma unroll
                for (int i = 0; i < 4; ++i) {
                    const int n = n0 + (i & 1);
                    const int mo = (i >> 1) * 8;
                    float v0 = tanh_fast(c[0][i] + c2[0][i] + xc[i]);
                    float v1 = tanh_fast(c[1][i] + c2[1][i] + xd[i]);
                    hsA[wr][n][m0 + mo]      = __float2half_rn(v0);
                    hsA[wr][n][m0 + 16 + mo] = __float2half_rn(v1);
                }
                xc0 = xn0; xc1 = xn1;
            }
            __syncthreads();
            if (tid == 0) st_rel(&g_progA[cid], u);
        }
    }
    // ======================= Stage B: xp1 projection ========================
    else if (role == 1) {
        uint32_t afr[2][16][4];
        load_frags(afr, Wih1, w, grp, tid4);
        float bias[2][2];
        #pragma unroll
        for (int mt = 0; mt < 2; ++mt)
            #pragma unroll
            for (int ih = 0; ih < 2; ++ih) {
                const int m = m0 + mt * 16 + ih * 8;
                bias[mt][ih] = b_ih[HD + m] + b_hh[HD + m];
            }

        const int ln = tid >> 5, kb = (tid & 31) * 8;

        // skid: let A run ahead so per-pair polls hit on the first try
        if (tid == 0) prewait(&g_progA[cid], 32);

        for (int tp = 0; tp < TLEN; tp += 2) {
            if (tid == 0) { while (ld_acq(&g_progA[cid]) < tp + 2) {} }
            __syncthreads();

            // stage two h0 tiles into smem (coalesced)
            uint4 v0 = *(const uint4*)((const char*)g_H0h +
                        ((((size_t)tp * 4 + cid) * 8 + ln) * 512) + kb * 2);
            uint4 v1 = *(const uint4*)((const char*)g_H0h +
                        ((((size_t)(tp + 1) * 4 + cid) * 8 + ln) * 512) + kb * 2);
            *(uint4*)&hsA[0][ln][kb] = v0;
            *(uint4*)&hsA[1][ln][kb] = v1;
            __syncthreads();

            #pragma unroll
            for (int s = 0; s < 2; ++s) {
                float c[2][4] = {}, c2[2][4] = {};
                #pragma unroll
                for (int kt = 0; kt < 16; ++kt) {
                    const __half* bp = &hsA[s][grp][kt * 16 + tid4 * 2];
                    const uint32_t bf0 = *(const uint32_t*)bp;
                    const uint32_t bf1 = *(const uint32_t*)(bp + 8);
                    if (kt & 1) { HMMA(c2[0], afr[0][kt], bf0, bf1); HMMA(c2[1], afr[1][kt], bf0, bf1); }
                    else        { HMMA(c [0], afr[0][kt], bf0, bf1); HMMA(c [1], afr[1][kt], bf0, bf1); }
                }
                float* ob = g_Xp1 + (((size_t)(tp + s) * 4 + cid) * 8 + w) * 256 + lane * 8;
                float4 o0, o1;
                ((float*)&o0)[0] = c[0][0] + c2[0][0] + bias[0][0];
                ((float*)&o0)[1] = c[0][1] + c2[0][1] + bias[0][0];
                ((float*)&o0)[2] = c[0][2] + c2[0][2] + bias[0][1];
                ((float*)&o0)[3] = c[0][3] + c2[0][3] + bias[0][1];
                ((float*)&o1)[0] = c[1][0] + c2[1][0] + bias[1][0];
                ((float*)&o1)[1] = c[1][1] + c2[1][1] + bias[1][0];
                ((float*)&o1)[2] = c[1][2] + c2[1][2] + bias[1][1];
                ((float*)&o1)[3] = c[1][3] + c2[1][3] + bias[1][1];
                *(float4*)ob = o0;
                *(float4*)(ob + 4) = o1;
            }
            __syncthreads();
            if (tid == 0) st_rel(&g_progB[cid], tp + 2);
        }
    }
    // ======================= Stage C: layer-1 recurrence ====================
    else {
        uint32_t afr[2][16][4];
        load_frags(afr, Whh1, w, grp, tid4);

        const float* h0l1 = h0all + (size_t)NB * HD;
        for (int idx = tid; idx < 8 * HD; idx += 256) {
            const int n = idx >> 8, k = idx & 255;
            hsA[0][n][k] = __float2half_rn(h0l1[(size_t)(b0 + n) * HD + k]);
        }
        __syncthreads();

        // skid: let A+B run 64 steps ahead so per-step polls hit first try
        prewait(&g_progB[cid], 64);
        const size_t fb = ((size_t)cid * 8 + w) * 256 + lane * 8;
        float4 xc0 = *(const float4*)(g_Xp1 + fb);
        float4 xc1 = *(const float4*)(g_Xp1 + fb + 4);

        for (int u = 0; u <= TLEN; ++u) {
            const int rd = u & 1, wr = rd ^ 1;

            // flush Out(u-1): coalesced fp32 copy from staging buffer
            if (u > 0) {
                const int n = tid >> 5, kb = (tid & 31) * 8;
                float4 a = *(const float4*)&obuf[rd][n][kb];
                float4 b = *(const float4*)&obuf[rd][n][kb + 4];
                float* dst = Out + ((size_t)(u - 1) * NB + b0 + n) * HD + kb;
                *(float4*)dst = a;
                *(float4*)(dst + 4) = b;
            }

            if (u < TLEN) {
                float c[2][4] = {}, c2[2][4] = {};
                #pragma unroll
                for (int kt = 0; kt < 16; ++kt) {
                    const __half* bp = &hsA[rd][grp][kt * 16 + tid4 * 2];
                    const uint32_t bf0 = *(const uint32_t*)bp;
                    const uint32_t bf1 = *(const uint32_t*)(bp + 8);
                    if (kt & 1) { HMMA(c2[0], afr[0][kt], bf0, bf1); HMMA(c2[1], afr[1][kt], bf0, bf1); }
                    else        { HMMA(c [0], afr[0][kt], bf0, bf1); HMMA(c [1], afr[1][kt], bf0, bf1); }
                }
                // prefetch xp1(u+1) behind the MMAs (acquire check, normally 1st-try)
                const int tn = (u + 1 < TLEN) ? u + 1 : TLEN - 1;
                while (ld_acq(&g_progB[cid]) < tn + 1) {}
                const float* pn = g_Xp1 + ((size_t)tn * 4 * 8 * 32 * 8) + fb;
                float4 xn0 = *(const float4*)pn;
                float4 xn1 = *(const float4*)(pn + 4);

                const float* xc = (const float*)&xc0;
                const float* xd = (const float*)&xc1;
                #pragma unroll
                for (int i = 0; i < 4; ++i) {
                    const int n = n0 + (i & 1);
                    const int mo = (i >> 1) * 8;
                    float v0 = tanh_fast(c[0][i] + c2[0][i] + xc[i]);
                    float v1 = tanh_fast(c[1][i] + c2[1][i] + xd[i]);
                    hsA[wr][n][m0 + mo]       = __float2half_rn(v0);
                    hsA[wr][n][m0 + 16 + mo]  = __float2half_rn(v1);
                    obuf[wr][n][m0 + mo]      = v0;
                    obuf[wr][n][m0 + 16 + mo] = v1;
                }
                xc0 = xn0; xc1 = xn1;
            }
            __syncthreads();
        }
    }
}

// --------------------------- input-path GEMM (layer 0) ----------------------
// Xp0[t,b,h] = sum_d x[t,b,d] * W_ih0[h,d] + bi[h] + bh[h], stored FRAG-LAYOUT.
#define BM 64
#define BN 64
#define BK 16

__global__ void __launch_bounds__(256) gemm_xw_kernel(
    const float* __restrict__ In, const float* __restrict__ W,
    const float* __restrict__ bi, const float* __restrict__ bh,
    float* __restrict__ OutF)
{
    __shared__ float As[BM][BK + 1];
    __shared__ float Bs[BN][BK + 1];

    const int row0 = blockIdx.y * BM;
    const int col0 = blockIdx.x * BN;
    const int tid  = threadIdx.x;

    if (blockIdx.x == 0 && blockIdx.y == 0 && tid == 0) {
        #pragma unroll
        for (int i = 0; i < 4; ++i) { g_progA[i] = 0; g_progB[i] = 0; }
    }

    const int tx = tid & 15;
    const int ty = tid >> 4;

    float acc[4][4] = {};

    const int lr = tid >> 2;
    const int lc = (tid & 3) << 2;

    for (int k0 = 0; k0 < HD; k0 += BK) {
        float4 a = *(const float4*)&In[(size_t)(row0 + lr) * HD + k0 + lc];
        float4 b = *(const float4*)&W [(size_t)(col0 + lr) * HD + k0 + lc];
        As[lr][lc] = a.x; As[lr][lc + 1] = a.y; As[lr][lc + 2] = a.z; As[lr][lc + 3] = a.w;
        Bs[lr][lc] = b.x; Bs[lr][lc + 1] = b.y; Bs[lr][lc + 2] = b.z; Bs[lr][lc + 3] = b.w;
        __syncthreads();
        #pragma unroll
        for (int kk = 0; kk < BK; ++kk) {
            float av[4], bv[4];
            #pragma unroll
            for (int i = 0; i < 4; ++i) av[i] = As[ty * 4 + i][kk];
            #pragma unroll
            for (int j = 0; j < 4; ++j) bv[j] = Bs[tx * 4 + j][kk];
            #pragma unroll
            for (int i = 0; i < 4; ++i)
                #pragma unroll
                for (int j = 0; j < 4; ++j) acc[i][j] += av[i] * bv[j];
        }
        __syncthreads();
    }

    #pragma unroll
    for (int j = 0; j < 4; ++j) {
        const int h = col0 + tx * 4 + j;
        const float bias = bi[h] + bh[h];
        const int wA  = h >> 5, mt = (h >> 4) & 1, ihi = (h >> 3) & 1, grpA = h & 7;
        #pragma unroll
        for (int i = 0; i < 4; ++i) {
            const int r = row0 + ty * 4 + i;
            const int t = r >> 5, b = r & 31;
            const int cta = b >> 3, n = b & 7;
            const int laneA = grpA * 4 + (n >> 1);
            const int jA = mt * 4 + ihi * 2 + (n & 1);
            OutF[((((size_t)t * 4 + cta) * 8 + wA) * 32 + laneA) * 8 + jA] = acc[i][j] + bias;
        }
    }
}

// -------------------------------- launcher ----------------------------------
extern "C" void kernel_launch(void* const* d_in, const int* in_sizes, int n_in,
                              void* d_out, int out_size) {
    const float* x    = (const float*)d_in[0];  // [T,B,D]
    const float* W_ih = (const float*)d_in[1];  // [L,H,D]
    const float* W_hh = (const float*)d_in[2];  // [L,H,H]
    const float* b_ih = (const float*)d_in[3];  // [L,H]
    const float* b_hh = (const float*)d_in[4];  // [L,H]
    const float* h0   = (const float*)d_in[5];  // [L,B,H]
    float* out = (float*)d_out;                 // [T,B,H]

    float* Xp0 = nullptr;
    cudaGetSymbolAddress((void**)&Xp0, g_Xp0);

    const dim3 gemm_grid(HD / BN, (TLEN * NB) / BM);

    gemm_xw_kernel<<<gemm_grid, 256>>>(x, W_ih, b_ih, b_hh, Xp0);
    rnn_fused_kernel<<<12, 256>>>(W_hh, W_hh + HD * HD, W_ih + HD * HD,
                                  b_ih, b_hh, h0, out);
}

// round 6
// speedup vs baseline: 1.8916x; 1.0679x over previous
#include <cuda_runtime.h>
#include <cuda_fp16.h>
#include <cstdint>
#include <cstddef>

#define TLEN 4096
#define NB   32
#define HD   256
#define HS   264   // smem halves per n-row (256 + 8 pad, conflict-free b-frags)

// Scratch (device globals: allocation-free rule)
static __device__ __align__(256) float  g_Xp0[(size_t)TLEN * NB * HD]; // frag-layout preacts L0
static __device__ __align__(256) float  g_Xp1[(size_t)TLEN * NB * HD]; // frag-layout preacts L1
static __device__ __align__(256) __half g_H0h[(size_t)TLEN * NB * HD]; // L0 hidden, [t][cid][n][256] fp16
static __device__ int g_progA[4];
static __device__ int g_progB[4];

// ---------------------------------------------------------------------------
__device__ __forceinline__ float tanh_mufu(float x) {
    float y;
    asm("tanh.approx.f32 %0, %1;" : "=f"(y) : "f"(x));
    return y;
}
__device__ __forceinline__ uint32_t pack_h2(float lo, float hi) {
    __half2 h = __floats2half2_rn(lo, hi);
    return *reinterpret_cast<uint32_t*>(&h);
}
__device__ __forceinline__ uint32_t smem_u32(const void* p) {
    uint32_t a;
    asm("{ .reg .u64 t; cvta.to.shared.u64 t, %1; cvt.u32.u64 %0, t; }" : "=r"(a) : "l"(p));
    return a;
}
__device__ __forceinline__ int ld_acq(const int* p) {
    int v;
    asm volatile("ld.acquire.gpu.global.s32 %0, [%1];" : "=r"(v) : "l"(p));
    return v;
}
__device__ __forceinline__ void st_rel(int* p, int v) {
    asm volatile("st.release.gpu.global.s32 [%0], %1;" :: "l"(p), "r"(v));
}
__device__ __forceinline__ void prewait(const int* p, int v) {
    while (ld_acq(p) < v) { __nanosleep(200); }
}
#define HMMA(acc, af, bf0, bf1)                                               \
    asm volatile(                                                             \
        "mma.sync.aligned.m16n8k16.row.col.f32.f16.f16.f32 "                  \
        "{%0,%1,%2,%3}, {%4,%5,%6,%7}, {%8,%9}, {%0,%1,%2,%3};"               \
        : "+f"((acc)[0]), "+f"((acc)[1]), "+f"((acc)[2]), "+f"((acc)[3])      \
        : "r"((af)[0]), "r"((af)[1]), "r"((af)[2]), "r"((af)[3]),             \
          "r"(bf0), "r"(bf1))
#define LDSM4(r0, r1, r2, r3, a)                                              \
    asm volatile("ldmatrix.sync.aligned.m8n8.x4.shared.b16 {%0,%1,%2,%3}, [%4];" \
        : "=r"(r0), "=r"(r1), "=r"(r2), "=r"(r3) : "r"(a))

// 16-HMMA step body: B frags via ldmatrix.x4 from smem buffer at byte addr ab.
#define MMA_STEP(c, c2, afr, ab)                                              \
    do {                                                                      \
        _Pragma("unroll")                                                     \
        for (int kk = 0; kk < 8; ++kk) {                                      \
            uint32_t b0, b1, b2, b3;                                          \
            LDSM4(b0, b1, b2, b3, (ab) + kk * 64);                            \
            HMMA((c)[0],  (afr)[0][2 * kk],     b0, b1);                      \
            HMMA((c)[1],  (afr)[1][2 * kk],     b0, b1);                      \
            HMMA((c2)[0], (afr)[0][2 * kk + 1], b2, b3);                      \
            HMMA((c2)[1], (afr)[1][2 * kk + 1], b2, b3);                      \
        }                                                                     \
    } while (0)

// Load register-resident A fragments for a 32-row slice of a 256x256 fp32 weight.
__device__ __forceinline__ void load_frags(uint32_t afr[2][16][4],
                                           const float* __restrict__ W,
                                           int w, int grp, int tid4) {
    #pragma unroll
    for (int mt = 0; mt < 2; ++mt) {
        const int r0 = w * 32 + mt * 16 + grp;
        #pragma unroll
        for (int kt = 0; kt < 16; ++kt) {
            const int k0 = kt * 16 + tid4 * 2;
            const float* p0 = W + (size_t)r0 * HD + k0;
            const float* p1 = W + (size_t)(r0 + 8) * HD + k0;
            afr[mt][kt][0] = pack_h2(p0[0], p0[1]);
            afr[mt][kt][1] = pack_h2(p1[0], p1[1]);
            afr[mt][kt][2] = pack_h2(p0[8], p0[9]);
            afr[mt][kt][3] = pack_h2(p1[8], p1[9]);
        }
    }
}

// ---------------------------------------------------------------------------
// Fused 3-stage pipelined kernel.  grid = 12 CTAs x 256 threads:
//   CTA 0-3  (A): layer-0 recurrence, publishes h0(t) fp16 tiles
//   CTA 4-7  (B): projection xp1(t) = W_ih1 * h0(t) + bias (double-stepped)
//   CTA 8-11 (C): layer-1 recurrence, writes final Out
__global__ void __launch_bounds__(256, 1) rnn_fused_kernel(
    const float* __restrict__ Whh0, const float* __restrict__ Whh1,
    const float* __restrict__ Wih1,
    const float* __restrict__ b_ih, const float* __restrict__ b_hh,
    const float* __restrict__ h0all, float* __restrict__ Out)
{
    __shared__ __align__(16) __half hsA[2][8][HS];   // A/C: h state (dbl-buf); B: staged tiles
    __shared__ __align__(16) float  obuf[2][8][HS];  // C only: output staging

    const int tid  = threadIdx.x;
    const int w    = tid >> 5;
    const int lane = tid & 31;
    const int grp  = lane >> 2;
    const int tid4 = lane & 3;
    const int role = blockIdx.x >> 2;   // 0=A, 1=B, 2=C
    const int cid  = blockIdx.x & 3;
    const int b0   = cid * 8;
    const int m0   = w * 32 + grp;
    const int n0   = tid4 * 2;

    // ldmatrix lane address base (buffer 0): row = lane&7, 16B chunk = lane>>3
    const uint32_t hs_base = smem_u32(&hsA[0][0][0]);
    const uint32_t lsm0 = hs_base + (uint32_t)(lane & 7) * (HS * 2) + (uint32_t)(lane >> 3) * 16;
    const uint32_t BUFB = 8 * HS * 2;   // bytes per h buffer

    // ======================= Stage A: layer-0 recurrence ====================
    if (role == 0) {
        uint32_t afr[2][16][4];
        load_frags(afr, Whh0, w, grp, tid4);

        for (int idx = tid; idx < 8 * HD; idx += 256) {
            const int n = idx >> 8, k = idx & 255;
            hsA[0][n][k] = __float2half_rn(h0all[(size_t)(b0 + n) * HD + k]);
        }
        __syncthreads();

        const size_t fb = ((size_t)cid * 8 + w) * 256 + lane * 8;
        float4 xc0 = *(const float4*)(g_Xp0 + fb);
        float4 xc1 = *(const float4*)(g_Xp0 + fb + 4);

        for (int u = 0; u <= TLEN; ++u) {
            const int rd = u & 1, wr = rd ^ 1;

            // publish h0(u-1): coalesced fp16 tile copy smem -> gmem
            if (u > 0) {
                const int n = tid >> 5, kb = (tid & 31) * 8;
                uint4 v = *(const uint4*)&hsA[rd][n][kb];
                *(uint4*)((char*)g_H0h +
                          ((((size_t)(u - 1) * 4 + cid) * 8 + n) * 512) + kb * 2) = v;
            }

            if (u < TLEN) {
                float c[2][4] = {}, c2[2][4] = {};
                MMA_STEP(c, c2, afr, lsm0 + rd * BUFB);

                // prefetch next-step Xp0 behind the MMAs
                const int tn = (u + 1 < TLEN) ? u + 1 : TLEN - 1;
                const float* pn = g_Xp0 + ((size_t)tn * 4 * 8 * 32 * 8) + fb;
                float4 xn0 = *(const float4*)pn;
                float4 xn1 = *(const float4*)(pn + 4);

                const float* xc = (const float*)&xc0;  // [mt=0][i]
                const float* xd = (const float*)&xc1;  // [mt=1][i]
                #pragma unroll
                for (int i = 0; i < 4; ++i) {
                    const int n = n0 + (i & 1);
                    const int mo = (i >> 1) * 8;
                    float v0 = tanh_mufu(c[0][i] + c2[0][i] + xc[i]);
                    float v1 = tanh_mufu(c[1][i] + c2[1][i] + xd[i]);
                    hsA[wr][n][m0 + mo]      = __float2half_rn(v0);
                    hsA[wr][n][m0 + 16 + mo] = __float2half_rn(v1);
                }
                xc0 = xn0; xc1 = xn1;
            }
            __syncthreads();
            if (tid == 0) st_rel(&g_progA[cid], u);
        }
    }
    // ======================= Stage B: xp1 projection ========================
    else if (role == 1) {
        uint32_t afr[2][16][4];
        load_frags(afr, Wih1, w, grp, tid4);
        float bias[2][2];
        #pragma unroll
        for (int mt = 0; mt < 2; ++mt)
            #pragma unroll
            for (int ih = 0; ih < 2; ++ih) {
                const int m = m0 + mt * 16 + ih * 8;
                bias[mt][ih] = b_ih[HD + m] + b_hh[HD + m];
            }

        const int ln = tid >> 5, kb = (tid & 31) * 8;

        // skid: let A run ahead so per-pair polls hit on the first try
        if (tid == 0) prewait(&g_progA[cid], 32);

        for (int tp = 0; tp < TLEN; tp += 2) {
            if (tid == 0) { while (ld_acq(&g_progA[cid]) < tp + 2) {} }
            __syncthreads();

            // stage two h0 tiles into smem (coalesced)
            uint4 v0 = *(const uint4*)((const char*)g_H0h +
                        ((((size_t)tp * 4 + cid) * 8 + ln) * 512) + kb * 2);
            uint4 v1 = *(const uint4*)((const char*)g_H0h +
                        ((((size_t)(tp + 1) * 4 + cid) * 8 + ln) * 512) + kb * 2);
            *(uint4*)&hsA[0][ln][kb] = v0;
            *(uint4*)&hsA[1][ln][kb] = v1;
            __syncthreads();

            #pragma unroll
            for (int s = 0; s < 2; ++s) {
                float c[2][4] = {}, c2[2][4] = {};
                MMA_STEP(c, c2, afr, lsm0 + s * BUFB);

                float* ob = g_Xp1 + (((size_t)(tp + s) * 4 + cid) * 8 + w) * 256 + lane * 8;
                float4 o0, o1;
                ((float*)&o0)[0] = c[0][0] + c2[0][0] + bias[0][0];
                ((float*)&o0)[1] = c[0][1] + c2[0][1] + bias[0][0];
                ((float*)&o0)[2] = c[0][2] + c2[0][2] + bias[0][1];
                ((float*)&o0)[3] = c[0][3] + c2[0][3] + bias[0][1];
                ((float*)&o1)[0] = c[1][0] + c2[1][0] + bias[1][0];
                ((float*)&o1)[1] = c[1][1] + c2[1][1] + bias[1][0];
                ((float*)&o1)[2] = c[1][2] + c2[1][2] + bias[1][1];
                ((float*)&o1)[3] = c[1][3] + c2[1][3] + bias[1][1];
                *(float4*)ob = o0;
                *(float4*)(ob + 4) = o1;
            }
            __syncthreads();
            if (tid == 0) st_rel(&g_progB[cid], tp + 2);
        }
    }
    // ======================= Stage C: layer-1 recurrence ====================
    else {
        uint32_t afr[2][16][4];
        load_frags(afr, Whh1, w, grp, tid4);

        const float* h0l1 = h0all + (size_t)NB * HD;
        for (int idx = tid; idx < 8 * HD; idx += 256) {
            const int n = idx >> 8, k = idx & 255;
            hsA[0][n][k] = __float2half_rn(h0l1[(size_t)(b0 + n) * HD + k]);
        }
        __syncthreads();

        // skid: let A+B run 64 steps ahead so per-step polls hit first try
        prewait(&g_progB[cid], 64);
        const size_t fb = ((size_t)cid * 8 + w) * 256 + lane * 8;
        float4 xc0 = *(const float4*)(g_Xp1 + fb);
        float4 xc1 = *(const float4*)(g_Xp1 + fb + 4);

        for (int u = 0; u <= TLEN; ++u) {
            const int rd = u & 1, wr = rd ^ 1;

            // flush Out(u-1): coalesced fp32 copy from staging buffer
            if (u > 0) {
                const int n = tid >> 5, kb = (tid & 31) * 8;
                float4 a = *(const float4*)&obuf[rd][n][kb];
                float4 b = *(const float4*)&obuf[rd][n][kb + 4];
                float* dst = Out + ((size_t)(u - 1) * NB + b0 + n) * HD + kb;
                *(float4*)dst = a;
                *(float4*)(dst + 4) = b;
            }

            if (u < TLEN) {
                float c[2][4] = {}, c2[2][4] = {};
                MMA_STEP(c, c2, afr, lsm0 + rd * BUFB);

                // prefetch xp1(u+1) behind the MMAs (acquire check, normally 1st-try)
                const int tn = (u + 1 < TLEN) ? u + 1 : TLEN - 1;
                while (ld_acq(&g_progB[cid]) < tn + 1) {}
                const float* pn = g_Xp1 + ((size_t)tn * 4 * 8 * 32 * 8) + fb;
                float4 xn0 = *(const float4*)pn;
                float4 xn1 = *(const float4*)(pn + 4);

                const float* xc = (const float*)&xc0;
                const float* xd = (const float*)&xc1;
                #pragma unroll
                for (int i = 0; i < 4; ++i) {
                    const int n = n0 + (i & 1);
                    const int mo = (i >> 1) * 8;
                    float v0 = tanh_mufu(c[0][i] + c2[0][i] + xc[i]);
                    float v1 = tanh_mufu(c[1][i] + c2[1][i] + xd[i]);
                    hsA[wr][n][m0 + mo]       = __float2half_rn(v0);
                    hsA[wr][n][m0 + 16 + mo]  = __float2half_rn(v1);
                    obuf[wr][n][m0 + mo]      = v0;
                    obuf[wr][n][m0 + 16 + mo] = v1;
                }
                xc0 = xn0; xc1 = xn1;
            }
            __syncthreads();
        }
    }
}

// --------------------------- input-path GEMM (layer 0) ----------------------
// Xp0[t,b,h] = sum_d x[t,b,d] * W_ih0[h,d] + bi[h] + bh[h], stored FRAG-LAYOUT.
#define BM 64
#define BN 64
#define BK 16

__global__ void __launch_bounds__(256) gemm_xw_kernel(
    const float* __restrict__ In, const float* __restrict__ W,
    const float* __restrict__ bi, const float* __restrict__ bh,
    float* __restrict__ OutF)
{
    __shared__ float As[BM][BK + 1];
    __shared__ float Bs[BN][BK + 1];

    const int row0 = blockIdx.y * BM;
    const int col0 = blockIdx.x * BN;
    const int tid  = threadIdx.x;

    if (blockIdx.x == 0 && blockIdx.y == 0 && tid == 0) {
        #pragma unroll
        for (int i = 0; i < 4; ++i) { g_progA[i] = 0; g_progB[i] = 0; }
    }

    const int tx = tid & 15;
    const int ty = tid >> 4;

    float acc[4][4] = {};

    const int lr = tid >> 2;
    const int lc = (tid & 3) << 2;

    for (int k0 = 0; k0 < HD; k0 += BK) {
        float4 a = *(const float4*)&In[(size_t)(row0 + lr) * HD + k0 + lc];
        float4 b = *(const float4*)&W [(size_t)(col0 + lr) * HD + k0 + lc];
        As[lr][lc] = a.x; As[lr][lc + 1] = a.y; As[lr][lc + 2] = a.z; As[lr][lc + 3] = a.w;
        Bs[lr][lc] = b.x; Bs[lr][lc + 1] = b.y; Bs[lr][lc + 2] = b.z; Bs[lr][lc + 3] = b.w;
        __syncthreads();
        #pragma unroll
        for (int kk = 0; kk < BK; ++kk) {
            float av[4], bv[4];
            #pragma unroll
            for (int i = 0; i < 4; ++i) av[i] = As[ty * 4 + i][kk];
            #pragma unroll
            for (int j = 0; j < 4; ++j) bv[j] = Bs[tx * 4 + j][kk];
            #pragma unroll
            for (int i = 0; i < 4; ++i)
                #pragma unroll
                for (int j = 0; j < 4; ++j) acc[i][j] += av[i] * bv[j];
        }
        __syncthreads();
    }

    #pragma unroll
    for (int j = 0; j < 4; ++j) {
        const int h = col0 + tx * 4 + j;
        const float bias = bi[h] + bh[h];
        const int wA  = h >> 5, mt = (h >> 4) & 1, ihi = (h >> 3) & 1, grpA = h & 7;
        #pragma unroll
        for (int i = 0; i < 4; ++i) {
            const int r = row0 + ty * 4 + i;
            const int t = r >> 5, b = r & 31;
            const int cta = b >> 3, n = b & 7;
            const int laneA = grpA * 4 + (n >> 1);
            const int jA = mt * 4 + ihi * 2 + (n & 1);
            OutF[((((size_t)t * 4 + cta) * 8 + wA) * 32 + laneA) * 8 + jA] = acc[i][j] + bias;
        }
    }
}

// -------------------------------- launcher ----------------------------------
extern "C" void kernel_launch(void* const* d_in, const int* in_sizes, int n_in,
                              void* d_out, int out_size) {
    const float* x    = (const float*)d_in[0];  // [T,B,D]
    const float* W_ih = (const float*)d_in[1];  // [L,H,D]
    const float* W_hh = (const float*)d_in[2];  // [L,H,H]
    const float* b_ih = (const float*)d_in[3];  // [L,H]
    const float* b_hh = (const float*)d_in[4];  // [L,H]
    const float* h0   = (const float*)d_in[5];  // [L,B,H]
    float* out = (float*)d_out;                 // [T,B,H]

    float* Xp0 = nullptr;
    cudaGetSymbolAddress((void**)&Xp0, g_Xp0);

    const dim3 gemm_grid(HD / BN, (TLEN * NB) / BM);

    gemm_xw_kernel<<<gemm_grid, 256>>>(x, W_ih, b_ih, b_hh, Xp0);
    rnn_fused_kernel<<<12, 256>>>(W_hh, W_hh + HD * HD, W_ih + HD * HD,
                                  b_ih, b_hh, h0, out);
}

// round 7
// speedup vs baseline: 1.9012x; 1.0051x over previous
#include <cuda_runtime.h>
#include <cuda_fp16.h>
#include <cstdint>
#include <cstddef>

#define TLEN 4096
#define NB   32
#define HD   256
#define HS   264   // smem halves per n-row (256 + 8 pad, conflict-free b-frags)

// Scratch (device globals: allocation-free rule)
static __device__ __align__(256) float  g_Xp0[(size_t)TLEN * NB * HD]; // frag-layout preacts L0
static __device__ __align__(256) float  g_Xp1[(size_t)TLEN * NB * HD]; // frag-layout preacts L1
static __device__ __align__(256) __half g_H0h[(size_t)TLEN * NB * HD]; // L0 hidden, [t][cid][n][256] fp16
static __device__ int g_progA[4];
static __device__ int g_progB[4];

// ---------------------------------------------------------------------------
__device__ __forceinline__ float tanh_mufu(float x) {
    float y;
    asm("tanh.approx.f32 %0, %1;" : "=f"(y) : "f"(x));
    return y;
}
__device__ __forceinline__ uint32_t pack_h2(float lo, float hi) {
    __half2 h = __floats2half2_rn(lo, hi);
    return *reinterpret_cast<uint32_t*>(&h);
}
__device__ __forceinline__ uint32_t smem_u32(const void* p) {
    uint32_t a;
    asm("{ .reg .u64 t; cvta.to.shared.u64 t, %1; cvt.u32.u64 %0, t; }" : "=r"(a) : "l"(p));
    return a;
}
__device__ __forceinline__ int ld_acq(const int* p) {
    int v;
    asm volatile("ld.acquire.gpu.global.s32 %0, [%1];" : "=r"(v) : "l"(p));
    return v;
}
__device__ __forceinline__ void st_rel(int* p, int v) {
    asm volatile("st.release.gpu.global.s32 [%0], %1;" :: "l"(p), "r"(v));
}
__device__ __forceinline__ int prewait(const int* p, int v) {
    int a;
    while ((a = ld_acq(p)) < v) { __nanosleep(200); }
    return a;
}
#define HMMA(acc, af, bf0, bf1)                                               \
    asm volatile(                                                             \
        "mma.sync.aligned.m16n8k16.row.col.f32.f16.f16.f32 "                  \
        "{%0,%1,%2,%3}, {%4,%5,%6,%7}, {%8,%9}, {%0,%1,%2,%3};"               \
        : "+f"((acc)[0]), "+f"((acc)[1]), "+f"((acc)[2]), "+f"((acc)[3])      \
        : "r"((af)[0]), "r"((af)[1]), "r"((af)[2]), "r"((af)[3]),             \
          "r"(bf0), "r"(bf1))
#define LDSM4(r0, r1, r2, r3, a)                                              \
    asm volatile("ldmatrix.sync.aligned.m8n8.x4.shared.b16 {%0,%1,%2,%3}, [%4];" \
        : "=r"(r0), "=r"(r1), "=r"(r2), "=r"(r3) : "r"(a))

// 16-HMMA step body: B frags via ldmatrix.x4 from smem buffer at byte addr ab.
#define MMA_STEP(c, c2, afr, ab)                                              \
    do {                                                                      \
        _Pragma("unroll")                                                     \
        for (int kk = 0; kk < 8; ++kk) {                                      \
            uint32_t b0, b1, b2, b3;                                          \
            LDSM4(b0, b1, b2, b3, (ab) + kk * 64);                            \
            HMMA((c)[0],  (afr)[0][2 * kk],     b0, b1);                      \
            HMMA((c)[1],  (afr)[1][2 * kk],     b0, b1);                      \
            HMMA((c2)[0], (afr)[0][2 * kk + 1], b2, b3);                      \
            HMMA((c2)[1], (afr)[1][2 * kk + 1], b2, b3);                      \
        }                                                                     \
    } while (0)

// Load register-resident A fragments for a 32-row slice of a 256x256 fp32 weight.
__device__ __forceinline__ void load_frags(uint32_t afr[2][16][4],
                                           const float* __restrict__ W,
                                           int w, int grp, int tid4) {
    #pragma unroll
    for (int mt = 0; mt < 2; ++mt) {
        const int r0 = w * 32 + mt * 16 + grp;
        #pragma unroll
        for (int kt = 0; kt < 16; ++kt) {
            const int k0 = kt * 16 + tid4 * 2;
            const float* p0 = W + (size_t)r0 * HD + k0;
            const float* p1 = W + (size_t)(r0 + 8) * HD + k0;
            afr[mt][kt][0] = pack_h2(p0[0], p0[1]);
            afr[mt][kt][1] = pack_h2(p1[0], p1[1]);
            afr[mt][kt][2] = pack_h2(p0[8], p0[9]);
            afr[mt][kt][3] = pack_h2(p1[8], p1[9]);
        }
    }
}

// ---------------------------------------------------------------------------
// Fused 3-stage pipelined kernel.  grid = 12 CTAs x 256 threads:
//   CTA 0-3  (A): layer-0 recurrence, publishes h0(t) fp16 tiles
//   CTA 4-7  (B): projection xp1(t) = W_ih1 * h0(t) + bias (double-stepped)
//   CTA 8-11 (C): layer-1 recurrence, writes final Out
__global__ void __launch_bounds__(256, 1) rnn_fused_kernel(
    const float* __restrict__ Whh0, const float* __restrict__ Whh1,
    const float* __restrict__ Wih1,
    const float* __restrict__ b_ih, const float* __restrict__ b_hh,
    const float* __restrict__ h0all, float* __restrict__ Out)
{
    __shared__ __align__(16) __half hsA[2][8][HS];   // A/C: h state (dbl-buf); B: staged tiles
    __shared__ __align__(16) float  obuf[2][8][HS];  // C only: output staging

    const int tid  = threadIdx.x;
    const int w    = tid >> 5;
    const int lane = tid & 31;
    const int grp  = lane >> 2;
    const int tid4 = lane & 3;
    const int role = blockIdx.x >> 2;   // 0=A, 1=B, 2=C
    const int cid  = blockIdx.x & 3;
    const int b0   = cid * 8;
    const int m0   = w * 32 + grp;
    const int n0   = tid4 * 2;

    // ldmatrix lane address base (buffer 0): row = lane&7, 16B chunk = lane>>3
    const uint32_t hs_base = smem_u32(&hsA[0][0][0]);
    const uint32_t lsm0 = hs_base + (uint32_t)(lane & 7) * (HS * 2) + (uint32_t)(lane >> 3) * 16;
    const uint32_t BUFB = 8 * HS * 2;   // bytes per h buffer

    // ======================= Stage A: layer-0 recurrence ====================
    if (role == 0) {
        uint32_t afr[2][16][4];
        load_frags(afr, Whh0, w, grp, tid4);

        for (int idx = tid; idx < 8 * HD; idx += 256) {
            const int n = idx >> 8, k = idx & 255;
            hsA[0][n][k] = __float2half_rn(h0all[(size_t)(b0 + n) * HD + k]);
        }
        __syncthreads();

        const size_t fb = ((size_t)cid * 8 + w) * 256 + lane * 8;
        float4 xc0 = *(const float4*)(g_Xp0 + fb);
        float4 xc1 = *(const float4*)(g_Xp0 + fb + 4);

        for (int u = 0; u <= TLEN; ++u) {
            const int rd = u & 1, wr = rd ^ 1;

            float c[2][4] = {}, c2[2][4] = {};
            if (u < TLEN) MMA_STEP(c, c2, afr, lsm0 + rd * BUFB);

            // publish h0(u-1) behind the MMA drain: coalesced fp16 smem -> gmem
            if (u > 0) {
                const int n = tid >> 5, kb = (tid & 31) * 8;
                uint4 v = *(const uint4*)&hsA[rd][n][kb];
                *(uint4*)((char*)g_H0h +
                          ((((size_t)(u - 1) * 4 + cid) * 8 + n) * 512) + kb * 2) = v;
            }

            if (u < TLEN) {
                // prefetch next-step Xp0 behind the MMAs
                const int tn = (u + 1 < TLEN) ? u + 1 : TLEN - 1;
                const float* pn = g_Xp0 + ((size_t)tn * 4 * 8 * 32 * 8) + fb;
                float4 xn0 = *(const float4*)pn;
                float4 xn1 = *(const float4*)(pn + 4);

                const float* xc = (const float*)&xc0;  // [mt=0][i]
                const float* xd = (const float*)&xc1;  // [mt=1][i]
                #pragma unroll
                for (int i = 0; i < 4; ++i) {
                    const int n = n0 + (i & 1);
                    const int mo = (i >> 1) * 8;
                    float v0 = tanh_mufu(c[0][i] + c2[0][i] + xc[i]);
                    float v1 = tanh_mufu(c[1][i] + c2[1][i] + xd[i]);
                    hsA[wr][n][m0 + mo]      = __float2half_rn(v0);
                    hsA[wr][n][m0 + 16 + mo] = __float2half_rn(v1);
                }
                xc0 = xn0; xc1 = xn1;
            }
            __syncthreads();
            // batched release: every 4 steps (+ final) — drains STG publishes
            if (tid == 0 && u > 0 && ((u & 3) == 0 || u == TLEN))
                st_rel(&g_progA[cid], u);
        }
    }
    // ======================= Stage B: xp1 projection ========================
    else if (role == 1) {
        uint32_t afr[2][16][4];
        load_frags(afr, Wih1, w, grp, tid4);
        float bias[2][2];
        #pragma unroll
        for (int mt = 0; mt < 2; ++mt)
            #pragma unroll
            for (int ih = 0; ih < 2; ++ih) {
                const int m = m0 + mt * 16 + ih * 8;
                bias[mt][ih] = b_ih[HD + m] + b_hh[HD + m];
            }

        const int ln = tid >> 5, kb = (tid & 31) * 8;

        // skid: let A run ahead; cache progress so per-pair polls are rare
        int avA = 0;
        if (tid == 0) avA = prewait(&g_progA[cid], 32);

        for (int tp = 0; tp < TLEN; tp += 2) {
            if (tid == 0 && avA < tp + 2) {
                while ((avA = ld_acq(&g_progA[cid])) < tp + 2) {}
            }
            __syncthreads();

            // stage two h0 tiles into smem (coalesced)
            uint4 v0 = *(const uint4*)((const char*)g_H0h +
                        ((((size_t)tp * 4 + cid) * 8 + ln) * 512) + kb * 2);
            uint4 v1 = *(const uint4*)((const char*)g_H0h +
                        ((((size_t)(tp + 1) * 4 + cid) * 8 + ln) * 512) + kb * 2);
            *(uint4*)&hsA[0][ln][kb] = v0;
            *(uint4*)&hsA[1][ln][kb] = v1;
            __syncthreads();

            #pragma unroll
            for (int s = 0; s < 2; ++s) {
                float c[2][4] = {}, c2[2][4] = {};
                MMA_STEP(c, c2, afr, lsm0 + s * BUFB);

                float* ob = g_Xp1 + (((size_t)(tp + s) * 4 + cid) * 8 + w) * 256 + lane * 8;
                float4 o0, o1;
                ((float*)&o0)[0] = c[0][0] + c2[0][0] + bias[0][0];
                ((float*)&o0)[1] = c[0][1] + c2[0][1] + bias[0][0];
                ((float*)&o0)[2] = c[0][2] + c2[0][2] + bias[0][1];
                ((float*)&o0)[3] = c[0][3] + c2[0][3] + bias[0][1];
                ((float*)&o1)[0] = c[1][0] + c2[1][0] + bias[1][0];
                ((float*)&o1)[1] = c[1][1] + c2[1][1] + bias[1][0];
                ((float*)&o1)[2] = c[1][2] + c2[1][2] + bias[1][1];
                ((float*)&o1)[3] = c[1][3] + c2[1][3] + bias[1][1];
                *(float4*)ob = o0;
                *(float4*)(ob + 4) = o1;
            }
            __syncthreads();
            // batched release: every 4 pairs (+ final)
            if (tid == 0 && (((tp + 2) & 7) == 0 || tp + 2 == TLEN))
                st_rel(&g_progB[cid], tp + 2);
        }
    }
    // ======================= Stage C: layer-1 recurrence ====================
    else {
        uint32_t afr[2][16][4];
        load_frags(afr, Whh1, w, grp, tid4);

        const float* h0l1 = h0all + (size_t)NB * HD;
        for (int idx = tid; idx < 8 * HD; idx += 256) {
            const int n = idx >> 8, k = idx & 255;
            hsA[0][n][k] = __float2half_rn(h0l1[(size_t)(b0 + n) * HD + k]);
        }
        __syncthreads();

        // skid: let A+B run ahead; cache progress (polls become rare)
        int avB = prewait(&g_progB[cid], 64);
        const size_t fb = ((size_t)cid * 8 + w) * 256 + lane * 8;
        float4 xc0 = *(const float4*)(g_Xp1 + fb);
        float4 xc1 = *(const float4*)(g_Xp1 + fb + 4);

        for (int u = 0; u <= TLEN; ++u) {
            const int rd = u & 1, wr = rd ^ 1;

            float c[2][4] = {}, c2[2][4] = {};
            if (u < TLEN) MMA_STEP(c, c2, afr, lsm0 + rd * BUFB);

            // flush Out(u-1) behind the MMA drain
            if (u > 0) {
                const int n = tid >> 5, kb = (tid & 31) * 8;
                float4 a = *(const float4*)&obuf[rd][n][kb];
                float4 b = *(const float4*)&obuf[rd][n][kb + 4];
                float* dst = Out + ((size_t)(u - 1) * NB + b0 + n) * HD + kb;
                *(float4*)dst = a;
                *(float4*)(dst + 4) = b;
            }

            if (u < TLEN) {
                // prefetch xp1(u+1): cached-progress check, poll only if behind
                const int tn = (u + 1 < TLEN) ? u + 1 : TLEN - 1;
                if (avB < tn + 1) {
                    while ((avB = ld_acq(&g_progB[cid])) < tn + 1) {}
                }
                const float* pn = g_Xp1 + ((size_t)tn * 4 * 8 * 32 * 8) + fb;
                float4 xn0 = *(const float4*)pn;
                float4 xn1 = *(const float4*)(pn + 4);

                const float* xc = (const float*)&xc0;
                const float* xd = (const float*)&xc1;
                #pragma unroll
                for (int i = 0; i < 4; ++i) {
                    const int n = n0 + (i & 1);
                    const int mo = (i >> 1) * 8;
                    float v0 = tanh_mufu(c[0][i] + c2[0][i] + xc[i]);
                    float v1 = tanh_mufu(c[1][i] + c2[1][i] + xd[i]);
                    hsA[wr][n][m0 + mo]       = __float2half_rn(v0);
                    hsA[wr][n][m0 + 16 + mo]  = __float2half_rn(v1);
                    obuf[wr][n][m0 + mo]      = v0;
                    obuf[wr][n][m0 + 16 + mo] = v1;
                }
                xc0 = xn0; xc1 = xn1;
            }
            __syncthreads();
        }
    }
}

// --------------------------- input-path GEMM (layer 0) ----------------------
// Xp0[t,b,h] = sum_d x[t,b,d] * W_ih0[h,d] + bi[h] + bh[h], stored FRAG-LAYOUT.
#define BM 64
#define BN 64
#define BK 16

__global__ void __launch_bounds__(256) gemm_xw_kernel(
    const float* __restrict__ In, const float* __restrict__ W,
    const float* __restrict__ bi, const float* __restrict__ bh,
    float* __restrict__ OutF)
{
    __shared__ float As[BM][BK + 1];
    __shared__ float Bs[BN][BK + 1];

    const int row0 = blockIdx.y * BM;
    const int col0 = blockIdx.x * BN;
    const int tid  = threadIdx.x;

    if (blockIdx.x == 0 && blockIdx.y == 0 && tid == 0) {
        #pragma unroll
        for (int i = 0; i < 4; ++i) { g_progA[i] = 0; g_progB[i] = 0; }
    }

    const int tx = tid & 15;
    const int ty = tid >> 4;

    float acc[4][4] = {};

    const int lr = tid >> 2;
    const int lc = (tid & 3) << 2;

    for (int k0 = 0; k0 < HD; k0 += BK) {
        float4 a = *(const float4*)&In[(size_t)(row0 + lr) * HD + k0 + lc];
        float4 b = *(const float4*)&W [(size_t)(col0 + lr) * HD + k0 + lc];
        As[lr][lc] = a.x; As[lr][lc + 1] = a.y; As[lr][lc + 2] = a.z; As[lr][lc + 3] = a.w;
        Bs[lr][lc] = b.x; Bs[lr][lc + 1] = b.y; Bs[lr][lc + 2] = b.z; Bs[lr][lc + 3] = b.w;
        __syncthreads();
        #pragma unroll
        for (int kk = 0; kk < BK; ++kk) {
            float av[4], bv[4];
            #pragma unroll
            for (int i = 0; i < 4; ++i) av[i] = As[ty * 4 + i][kk];
            #pragma unroll
            for (int j = 0; j < 4; ++j) bv[j] = Bs[tx * 4 + j][kk];
            #pragma unroll
            for (int i = 0; i < 4; ++i)
                #pragma unroll
                for (int j = 0; j < 4; ++j) acc[i][j] += av[i] * bv[j];
        }
        __syncthreads();
    }

    #pragma unroll
    for (int j = 0; j < 4; ++j) {
        const int h = col0 + tx * 4 + j;
        const float bias = bi[h] + bh[h];
        const int wA  = h >> 5, mt = (h >> 4) & 1, ihi = (h >> 3) & 1, grpA = h & 7;
        #pragma unroll
        for (int i = 0; i < 4; ++i) {
            const int r = row0 + ty * 4 + i;
            const int t = r >> 5, b = r & 31;
            const int cta = b >> 3, n = b & 7;
            const int laneA = grpA * 4 + (n >> 1);
            const int jA = mt * 4 + ihi * 2 + (n & 1);
            OutF[((((size_t)t * 4 + cta) * 8 + wA) * 32 + laneA) * 8 + jA] = acc[i][j] + bias;
        }
    }
}

// -------------------------------- launcher ----------------------------------
extern "C" void kernel_launch(void* const* d_in, const int* in_sizes, int n_in,
                              void* d_out, int out_size) {
    const float* x    = (const float*)d_in[0];  // [T,B,D]
    const float* W_ih = (const float*)d_in[1];  // [L,H,D]
    const float* W_hh = (const float*)d_in[2];  // [L,H,H]
    const float* b_ih = (const float*)d_in[3];  // [L,H]
    const float* b_hh = (const float*)d_in[4];  // [L,H]
    const float* h0   = (const float*)d_in[5];  // [L,B,H]
    float* out = (float*)d_out;                 // [T,B,H]

    float* Xp0 = nullptr;
    cudaGetSymbolAddress((void**)&Xp0, g_Xp0);

    const dim3 gemm_grid(HD / BN, (TLEN * NB) / BM);

    gemm_xw_kernel<<<gemm_grid, 256>>>(x, W_ih, b_ih, b_hh, Xp0);
    rnn_fused_kernel<<<12, 256>>>(W_hh, W_hh + HD * HD, W_ih + HD * HD,
                                  b_ih, b_hh, h0, out);
}